// round 15
// baseline (speedup 1.0000x reference)
#include <cuda_runtime.h>

#define NTOK 4096

// scratch
__device__ unsigned g_xb[4][NTOK][128];    // X bf16x2 packed along k, [b][n][k/2]
__device__ unsigned g_wq[192][128];        // qkv_w bf16x2 packed along k, [o][k/2]
__device__ unsigned g_qt8[4][NTOK][16];    // Q e4m3 x4 packed along c, [n][c/4], unscaled
__device__ unsigned g_kt8[4][NTOK][16];    // K e4m3 x4 packed along c, [m][c/4]
__device__ unsigned g_vt[4][64][NTOK/2];   // V bf16x2 packed along m, [cv][m/2]
__device__ float g_att[4][64][NTOK];
__device__ float g_part[2][4][64][NTOK];   // split-KV unnormalized O
__device__ float g_l[2][4][NTOK];          // split-KV row sums

// ---- helpers ----
__device__ __forceinline__ float ex2f(float x){
  float r; asm("ex2.approx.f32 %0, %1;" : "=f"(r) : "f"(x)); return r;
}
__device__ __forceinline__ unsigned pack_bf16(float lo, float hi){
  unsigned r; asm("cvt.rn.bf16x2.f32 %0, %1, %2;" : "=r"(r) : "f"(hi), "f"(lo));
  return r;
}
__device__ __forceinline__ unsigned short pack_e4m3(float lo, float hi){
  unsigned short r;
  asm("cvt.rn.satfinite.e4m3x2.f32 %0, %1, %2;" : "=h"(r) : "f"(hi), "f"(lo));
  return r;
}
__device__ __forceinline__ void mma_tf32(float d[4],
    unsigned a0, unsigned a1, unsigned a2, unsigned a3,
    unsigned b0, unsigned b1){
  asm("mma.sync.aligned.m16n8k8.row.col.f32.tf32.tf32.f32 "
      "{%0,%1,%2,%3}, {%4,%5,%6,%7}, {%8,%9}, {%0,%1,%2,%3};"
      : "+f"(d[0]), "+f"(d[1]), "+f"(d[2]), "+f"(d[3])
      : "r"(a0), "r"(a1), "r"(a2), "r"(a3), "r"(b0), "r"(b1));
}
__device__ __forceinline__ void mma_bf16(float d[4],
    unsigned a0, unsigned a1, unsigned a2, unsigned a3,
    unsigned b0, unsigned b1){
  asm("mma.sync.aligned.m16n8k16.row.col.f32.bf16.bf16.f32 "
      "{%0,%1,%2,%3}, {%4,%5,%6,%7}, {%8,%9}, {%0,%1,%2,%3};"
      : "+f"(d[0]), "+f"(d[1]), "+f"(d[2]), "+f"(d[3])
      : "r"(a0), "r"(a1), "r"(a2), "r"(a3), "r"(b0), "r"(b1));
}
__device__ __forceinline__ void mma_fp8(float d[4],
    unsigned a0, unsigned a1, unsigned a2, unsigned a3,
    unsigned b0, unsigned b1){
  asm("mma.sync.aligned.m16n8k32.row.col.f32.e4m3.e4m3.f32 "
      "{%0,%1,%2,%3}, {%4,%5,%6,%7}, {%8,%9}, {%0,%1,%2,%3};"
      : "+f"(d[0]), "+f"(d[1]), "+f"(d[2]), "+f"(d[3])
      : "r"(a0), "r"(a1), "r"(a2), "r"(a3), "r"(b0), "r"(b1));
}
#define U(x) __float_as_uint(x)

__device__ __forceinline__ unsigned smem_u32(const void* p){
  unsigned a;
  asm("{ .reg .u64 t; cvta.to.shared.u64 t, %1; cvt.u32.u64 %0, t; }"
      : "=r"(a) : "l"(p));
  return a;
}
__device__ __forceinline__ void cp_async16(unsigned saddr, const void* gptr){
  asm volatile("cp.async.cg.shared.global [%0], [%1], 16;"
               :: "r"(saddr), "l"(gptr));
}
#define CP_COMMIT asm volatile("cp.async.commit_group;" ::: "memory")
#define CP_WAIT0  asm volatile("cp.async.wait_group 0;" ::: "memory")
#define CP_WAIT1  asm volatile("cp.async.wait_group 1;" ::: "memory")

// ---------------------------------------------------------------------------
// X pre-pass: transpose [b][k][n] fp32 -> [b][n][k/2] bf16x2 words.
// grid (NTOK/64, 256/64, B), 256 threads, 64x64 tile.
// ---------------------------------------------------------------------------
__global__ __launch_bounds__(256)
void xprep_kernel(const float* __restrict__ x)
{
  __shared__ float sm[64*68];
  const int b = blockIdx.z, kt = blockIdx.y, n0 = blockIdx.x * 64;
  const float* Xb = x + ((size_t)b*256 + kt*64) * NTOK;
  const int tid = threadIdx.x;
  #pragma unroll
  for (int i = tid; i < 1024; i += 256){
    int k = i >> 4, f = i & 15;
    *(float4*)(sm + k*68 + 4*f) = *(const float4*)(Xb + (size_t)k*NTOK + n0 + 4*f);
  }
  __syncthreads();
  #pragma unroll
  for (int i = tid; i < 2048; i += 256){
    int n = i >> 5, w = i & 31;
    g_xb[b][n0 + n][kt*32 + w] =
        pack_bf16(sm[(2*w)*68 + n], sm[(2*w + 1)*68 + n]);
  }
}

// ---------------------------------------------------------------------------
// W pre-pass: qkv_w [192][256] fp32 -> [o][k/2] bf16x2.  grid 24, 256 thr.
// ---------------------------------------------------------------------------
__global__ __launch_bounds__(256)
void wprep_kernel(const float* __restrict__ W)
{
  #pragma unroll
  for (int j = 0; j < 4; j++){
    int idx = blockIdx.x*1024 + j*256 + threadIdx.x;
    int o = idx >> 7, w = idx & 127;
    float2 v = *(const float2*)(W + (size_t)o*256 + 2*w);
    g_wq[o][w] = pack_bf16(v.x, v.y);
  }
}

// ---------------------------------------------------------------------------
// QKV projection, all-bf16 m16n8k16, 3-stage cp.async, k-chunk 64.
// grid (NTOK/64, 3, B), 256 threads (8 warps: wm=warp&3, wn=warp>>2).
// y==0 -> Q e4m3 pack -> g_qt8; y==1 -> K -> g_kt8; y==2 -> V bf16 -> g_vt.
// ---------------------------------------------------------------------------
#define QK_STR 36
#define QSTG (2*64*QK_STR)    // words per stage: 4608

__global__ __launch_bounds__(256)
void qkv_bf16_kernel(const float* __restrict__ bias)
{
  extern __shared__ unsigned su[];
  const int b = blockIdx.z;
  const int o0 = blockIdx.y * 64, n0 = blockIdx.x * 64;
  const int tid = threadIdx.x, warp = tid >> 5, lane = tid & 31;
  const int g = lane >> 2, t = lane & 3;
  const int wm = warp & 3, wn = warp >> 2;

  float acc[4][4];
  #pragma unroll
  for (int nf = 0; nf < 4; nf++)
    #pragma unroll
    for (int j = 0; j < 4; j++) acc[nf][j] = 0.f;

  #pragma unroll
  for (int s = 0; s < 2; s++){
    unsigned* ws = su + s*QSTG;
    unsigned* xs = ws + 64*QK_STR;
    #pragma unroll
    for (int i = tid; i < 512; i += 256){
      int row = i >> 3, j = i & 7;
      cp_async16(smem_u32(ws + row*QK_STR + 4*j), &g_wq[o0 + row][s*32 + 4*j]);
      cp_async16(smem_u32(xs + row*QK_STR + 4*j), &g_xb[b][n0 + row][s*32 + 4*j]);
    }
    CP_COMMIT;
  }

  for (int ki = 0; ki < 4; ki++){
    if (ki == 3){ CP_WAIT0; } else { CP_WAIT1; }
    __syncthreads();
    if (ki + 2 < 4){
      unsigned* ws = su + ((ki + 2) % 3)*QSTG;
      unsigned* xs = ws + 64*QK_STR;
      #pragma unroll
      for (int i = tid; i < 512; i += 256){
        int row = i >> 3, j = i & 7;
        cp_async16(smem_u32(ws + row*QK_STR + 4*j), &g_wq[o0 + row][(ki+2)*32 + 4*j]);
        cp_async16(smem_u32(xs + row*QK_STR + 4*j), &g_xb[b][n0 + row][(ki+2)*32 + 4*j]);
      }
      CP_COMMIT;
    }
    const unsigned* ws = su + (ki % 3)*QSTG;
    const unsigned* xs = ws + 64*QK_STR;
    #pragma unroll
    for (int kk = 0; kk < 4; kk++){
      unsigned a0 = ws[(16*wm + g    )*QK_STR + 8*kk + t];
      unsigned a1 = ws[(16*wm + g + 8)*QK_STR + 8*kk + t];
      unsigned a2 = ws[(16*wm + g    )*QK_STR + 8*kk + t + 4];
      unsigned a3 = ws[(16*wm + g + 8)*QK_STR + 8*kk + t + 4];
      #pragma unroll
      for (int nf = 0; nf < 4; nf++){
        unsigned b0 = xs[(32*wn + 8*nf + g)*QK_STR + 8*kk + t];
        unsigned b1 = xs[(32*wn + 8*nf + g)*QK_STR + 8*kk + t + 4];
        mma_bf16(acc[nf], a0, a1, a2, a3, b0, b1);
      }
    }
  }
  const int r0 = o0 + 16*wm + g, r1 = r0 + 8;
  const float bb0 = bias[r0], bb1 = bias[r1];

  if (blockIdx.y == 2){
    // V: pack along n (columns), write g_vt[b][cv][m/2]
    int cv0 = 16*wm + g, cv1 = cv0 + 8;
    #pragma unroll
    for (int nf = 0; nf < 4; nf++){
      int wc = (n0 >> 1) + 16*wn + 4*nf + t;
      g_vt[b][cv0][wc] = pack_bf16(acc[nf][0] + bb0, acc[nf][1] + bb0);
      g_vt[b][cv1][wc] = pack_bf16(acc[nf][2] + bb1, acc[nf][3] + bb1);
    }
    return;
  }
  // Q/K: e4m3-pack 4 consecutive o-rows per u32 word, layout [n][c/4].
  unsigned* dst = (blockIdx.y == 0) ? &g_qt8[b][0][0] : &g_kt8[b][0][0];
  const int jgrp = g >> 2;
  const bool st = ((g & 3) == 0);
  #pragma unroll
  for (int nf = 0; nf < 4; nf++){
    int col = n0 + 32*wn + 8*nf + 2*t;
    float vals[4] = { acc[nf][0] + bb0, acc[nf][1] + bb0,
                      acc[nf][2] + bb1, acc[nf][3] + bb1 };
    #pragma unroll
    for (int q = 0; q < 4; q++){
      float v = vals[q];
      float o1 = __shfl_xor_sync(0xffffffffu, v, 4);
      unsigned short h16 = (g & 1) ? pack_e4m3(o1, v) : pack_e4m3(v, o1);
      unsigned hh = h16;
      unsigned o2 = __shfl_xor_sync(0xffffffffu, hh, 8);
      unsigned word = (g & 2) ? ((o2 & 0xFFFFu) | (hh << 16)) : (hh | (o2 << 16));
      if (st){
        int c = col + (q & 1);
        int w = 4*wm + ((q >> 1) ? 2 : 0) + jgrp;
        dst[(size_t)c*16 + w] = word;
      }
    }
  }
}

// ---------------------------------------------------------------------------
// Output projection, tf32, single-stage (K=64 fits smem whole).
// grid (NTOK/64, 4, B), 256 threads.
// ---------------------------------------------------------------------------
#define PW_STR 68
#define PX_STR 72

__global__ __launch_bounds__(256)
void proj_kernel(const float* __restrict__ W, const float* __restrict__ bias,
                 float* __restrict__ out)
{
  extern __shared__ float sp[];
  float* ws = sp;                 // 64*68
  float* xs = sp + 64*PW_STR;     // 64*72
  const int b = blockIdx.z;
  const int o0 = blockIdx.y * 64, n0 = blockIdx.x * 64;
  float* Ob = out + (size_t)b * 256 * NTOK;
  const int tid = threadIdx.x, warp = tid >> 5, lane = tid & 31;
  const int g = lane >> 2, t = lane & 3;
  const int wm = warp & 3, wn = warp >> 2;

  #pragma unroll
  for (int i = tid; i < 1024; i += 256){
    int row = i >> 4, f = i & 15;
    cp_async16(smem_u32(ws + row*PW_STR + 4*f), W + (size_t)(o0 + row)*64 + 4*f);
    cp_async16(smem_u32(xs + row*PX_STR + 4*f), &g_att[b][row][n0 + 4*f]);
  }
  CP_COMMIT; CP_WAIT0;
  __syncthreads();

  float acc[4][4];
  #pragma unroll
  for (int nf = 0; nf < 4; nf++)
    #pragma unroll
    for (int j = 0; j < 4; j++) acc[nf][j] = 0.f;

  #pragma unroll
  for (int kk = 0; kk < 8; kk++){
    unsigned a0 = U(ws[(16*wm + g    )*PW_STR + 8*kk + t]);
    unsigned a1 = U(ws[(16*wm + g + 8)*PW_STR + 8*kk + t]);
    unsigned a2 = U(ws[(16*wm + g    )*PW_STR + 8*kk + t + 4]);
    unsigned a3 = U(ws[(16*wm + g + 8)*PW_STR + 8*kk + t + 4]);
    #pragma unroll
    for (int nf = 0; nf < 4; nf++){
      unsigned b0 = U(xs[(8*kk + t    )*PX_STR + 32*wn + 8*nf + g]);
      unsigned b1 = U(xs[(8*kk + t + 4)*PX_STR + 32*wn + 8*nf + g]);
      mma_tf32(acc[nf], a0, a1, a2, a3, b0, b1);
    }
  }
  const int r0 = o0 + 16*wm + g, r1 = r0 + 8;
  const float bb0 = bias[r0], bb1 = bias[r1];
  #pragma unroll
  for (int nf = 0; nf < 4; nf++){
    int col = n0 + 32*wn + 8*nf + 2*t;
    *(float2*)(Ob + (size_t)r0*NTOK + col) = make_float2(acc[nf][0] + bb0, acc[nf][1] + bb0);
    *(float2*)(Ob + (size_t)r1*NTOK + col) = make_float2(acc[nf][2] + bb1, acc[nf][3] + bb1);
  }
}

// ---------------------------------------------------------------------------
// flash attention (unchanged from R13/R14): BM=128, 4 warps x 32 q-rows,
// BN=64, split-KV=2; fp8 S (m16n8k32), bf16 PV (m16n8k16), 3-stage cp.async.
// ---------------------------------------------------------------------------
#define FL_K 20
#define FL_V 36
#define KSTG_W (64*FL_K)
#define FSTG_W (KSTG_W + 64*FL_V)

__global__ __launch_bounds__(128)
void flash_kernel()
{
  extern __shared__ unsigned smu[];
  unsigned* qs  = smu;
  unsigned* stg = smu + 128*FL_K;

  const int b  = blockIdx.y;
  const int n0 = blockIdx.x * 128;
  const int h  = blockIdx.z;
  const unsigned* gq8 = &g_qt8[b][0][0];
  const unsigned* gk8 = &g_kt8[b][0][0];
  const unsigned* gvt = &g_vt[b][0][0];

  const int tid  = threadIdx.x;
  const int warp = tid >> 5, lane = tid & 31;
  const int g = lane >> 2, t = lane & 3;
  const int mbeg = h * 2048;
  const float SC = 0.125f * 1.44269504f;

  #pragma unroll
  for (int i = tid; i < 512; i += 128){
    int row = i >> 2, j = i & 3;
    cp_async16(smem_u32(qs + row*FL_K + 4*j), gq8 + (size_t)(n0 + row)*16 + 4*j);
  }
  #pragma unroll
  for (int s = 0; s < 2; s++){
    unsigned* kb = stg + s*FSTG_W;
    unsigned* vt = kb + KSTG_W;
    int mt = mbeg + 64*s;
    #pragma unroll
    for (int i = tid; i < 256; i += 128){
      int row = i >> 2, j = i & 3;
      cp_async16(smem_u32(kb + row*FL_K + 4*j), gk8 + (size_t)(mt + row)*16 + 4*j);
    }
    #pragma unroll
    for (int i = tid; i < 512; i += 128){
      int row = i >> 3, f = i & 7;
      cp_async16(smem_u32(vt + row*FL_V + 4*f),
                 gvt + (size_t)row*(NTOK/2) + (mt >> 1) + 4*f);
    }
    CP_COMMIT;
  }

  float rl0 = 0.f, rl1 = 0.f, rl2 = 0.f, rl3 = 0.f;
  float o0a[8][4], o1a[8][4];
  #pragma unroll
  for (int cf = 0; cf < 8; cf++)
    #pragma unroll
    for (int j = 0; j < 4; j++){ o0a[cf][j] = 0.f; o1a[cf][j] = 0.f; }

  const int w32 = 32*warp;
  const int ar0 = (w32 + g     ) * FL_K;
  const int ar1 = (w32 + g +  8) * FL_K;
  const int ar2 = (w32 + g + 16) * FL_K;
  const int ar3 = (w32 + g + 24) * FL_K;

  for (int it = 0; it < 32; it++){
    if (it == 31){ CP_WAIT0; } else { CP_WAIT1; }
    __syncthreads();
    if (it + 2 < 32){
      unsigned* kb = stg + ((it + 2) % 3)*FSTG_W;
      unsigned* vt = kb + KSTG_W;
      int mt = mbeg + 64*(it + 2);
      #pragma unroll
      for (int i = tid; i < 256; i += 128){
        int row = i >> 2, j = i & 3;
        cp_async16(smem_u32(kb + row*FL_K + 4*j), gk8 + (size_t)(mt + row)*16 + 4*j);
      }
      #pragma unroll
      for (int i = tid; i < 512; i += 128){
        int row = i >> 3, f = i & 7;
        cp_async16(smem_u32(vt + row*FL_V + 4*f),
                   gvt + (size_t)row*(NTOK/2) + (mt >> 1) + 4*f);
      }
      CP_COMMIT;
    }
    const unsigned* ks = stg + (it % 3)*FSTG_W;
    const unsigned* vt = ks + KSTG_W;

    float s0[8][4], s1[8][4];
    #pragma unroll
    for (int mf = 0; mf < 8; mf++)
      #pragma unroll
      for (int j = 0; j < 4; j++){ s0[mf][j] = 0.f; s1[mf][j] = 0.f; }

    #pragma unroll
    for (int kk = 0; kk < 2; kk++){
      unsigned a00 = qs[ar0 + 8*kk + t];
      unsigned a01 = qs[ar1 + 8*kk + t];
      unsigned a02 = qs[ar0 + 8*kk + t + 4];
      unsigned a03 = qs[ar1 + 8*kk + t + 4];
      unsigned a10 = qs[ar2 + 8*kk + t];
      unsigned a11 = qs[ar3 + 8*kk + t];
      unsigned a12 = qs[ar2 + 8*kk + t + 4];
      unsigned a13 = qs[ar3 + 8*kk + t + 4];
      #pragma unroll
      for (int mf = 0; mf < 8; mf++){
        unsigned b0 = ks[(8*mf + g)*FL_K + 8*kk + t];
        unsigned b1 = ks[(8*mf + g)*FL_K + 8*kk + t + 4];
        mma_fp8(s0[mf], a00, a01, a02, a03, b0, b1);
        mma_fp8(s1[mf], a10, a11, a12, a13, b0, b1);
      }
    }

    #pragma unroll
    for (int mf = 0; mf < 8; mf++){
      float p;
      p = ex2f(s0[mf][0]*SC); rl0 += p; s0[mf][0] = p;
      p = ex2f(s0[mf][1]*SC); rl0 += p; s0[mf][1] = p;
      p = ex2f(s0[mf][2]*SC); rl1 += p; s0[mf][2] = p;
      p = ex2f(s0[mf][3]*SC); rl1 += p; s0[mf][3] = p;
      p = ex2f(s1[mf][0]*SC); rl2 += p; s1[mf][0] = p;
      p = ex2f(s1[mf][1]*SC); rl2 += p; s1[mf][1] = p;
      p = ex2f(s1[mf][2]*SC); rl3 += p; s1[mf][2] = p;
      p = ex2f(s1[mf][3]*SC); rl3 += p; s1[mf][3] = p;
    }

    #pragma unroll
    for (int kk = 0; kk < 4; kk++){
      unsigned a00 = pack_bf16(s0[2*kk  ][0], s0[2*kk  ][1]);
      unsigned a01 = pack_bf16(s0[2*kk  ][2], s0[2*kk  ][3]);
      unsigned a02 = pack_bf16(s0[2*kk+1][0], s0[2*kk+1][1]);
      unsigned a03 = pack_bf16(s0[2*kk+1][2], s0[2*kk+1][3]);
      unsigned a10 = pack_bf16(s1[2*kk  ][0], s1[2*kk  ][1]);
      unsigned a11 = pack_bf16(s1[2*kk  ][2], s1[2*kk  ][3]);
      unsigned a12 = pack_bf16(s1[2*kk+1][0], s1[2*kk+1][1]);
      unsigned a13 = pack_bf16(s1[2*kk+1][2], s1[2*kk+1][3]);
      #pragma unroll
      for (int cf = 0; cf < 8; cf++){
        unsigned b0 = vt[(8*cf + g)*FL_V + 8*kk + t];
        unsigned b1 = vt[(8*cf + g)*FL_V + 8*kk + t + 4];
        mma_bf16(o0a[cf], a00, a01, a02, a03, b0, b1);
        mma_bf16(o1a[cf], a10, a11, a12, a13, b0, b1);
      }
    }
  }

  rl0 += __shfl_xor_sync(0xffffffffu, rl0, 1);
  rl0 += __shfl_xor_sync(0xffffffffu, rl0, 2);
  rl1 += __shfl_xor_sync(0xffffffffu, rl1, 1);
  rl1 += __shfl_xor_sync(0xffffffffu, rl1, 2);
  rl2 += __shfl_xor_sync(0xffffffffu, rl2, 1);
  rl2 += __shfl_xor_sync(0xffffffffu, rl2, 2);
  rl3 += __shfl_xor_sync(0xffffffffu, rl3, 1);
  rl3 += __shfl_xor_sync(0xffffffffu, rl3, 2);

  int ng = n0 + w32 + g;
  #pragma unroll
  for (int cf = 0; cf < 8; cf++){
    int c0 = 8*cf + 2*t;
    g_part[h][b][c0    ][ng     ] = o0a[cf][0];
    g_part[h][b][c0 + 1][ng     ] = o0a[cf][1];
    g_part[h][b][c0    ][ng +  8] = o0a[cf][2];
    g_part[h][b][c0 + 1][ng +  8] = o0a[cf][3];
    g_part[h][b][c0    ][ng + 16] = o1a[cf][0];
    g_part[h][b][c0 + 1][ng + 16] = o1a[cf][1];
    g_part[h][b][c0    ][ng + 24] = o1a[cf][2];
    g_part[h][b][c0 + 1][ng + 24] = o1a[cf][3];
  }
  if (t == 0){
    g_l[h][b][ng     ] = rl0;
    g_l[h][b][ng +  8] = rl1;
    g_l[h][b][ng + 16] = rl2;
    g_l[h][b][ng + 24] = rl3;
  }
}

// ---------------------------------------------------------------------------
// Combine: O = (p0 + p1) / (l0 + l1).  grid (64, B), 256 threads.
// ---------------------------------------------------------------------------
__global__ __launch_bounds__(256)
void combine_kernel()
{
  const int b = blockIdx.y;
  const int n = blockIdx.x * 64 + 4 * (threadIdx.x & 15);
  const int cg = threadIdx.x >> 4;
  float4 l0 = *(const float4*)&g_l[0][b][n];
  float4 l1 = *(const float4*)&g_l[1][b][n];
  float4 inv;
  inv.x = 1.f / (l0.x + l1.x);
  inv.y = 1.f / (l0.y + l1.y);
  inv.z = 1.f / (l0.z + l1.z);
  inv.w = 1.f / (l0.w + l1.w);
  #pragma unroll
  for (int cc = 0; cc < 4; cc++){
    int c = cg * 4 + cc;
    float4 p0 = *(const float4*)&g_part[0][b][c][n];
    float4 p1 = *(const float4*)&g_part[1][b][c][n];
    float4 o;
    o.x = (p0.x + p1.x) * inv.x;
    o.y = (p0.y + p1.y) * inv.y;
    o.z = (p0.z + p1.z) * inv.z;
    o.w = (p0.w + p1.w) * inv.w;
    *(float4*)&g_att[b][c][n] = o;
  }
}

// ---------------------------------------------------------------------------
extern "C" void kernel_launch(void* const* d_in, const int* in_sizes, int n_in,
                              void* d_out, int out_size)
{
  const float* x      = (const float*)d_in[0];
  const float* qkv_w  = (const float*)d_in[1];
  const float* qkv_b  = (const float*)d_in[2];
  const float* proj_w = (const float*)d_in[3];
  const float* proj_b = (const float*)d_in[4];
  float* out = (float*)d_out;

  const int qkv_smem   = 3 * QSTG * 4;                  // 55296 B
  const int flash_smem = (128*FL_K + 3*FSTG_W) * 4;     // 53248 B
  const int proj_smem  = (64*PW_STR + 64*PX_STR) * 4;   // 35840 B
  cudaFuncSetAttribute(qkv_bf16_kernel,
                       cudaFuncAttributeMaxDynamicSharedMemorySize, qkv_smem);
  cudaFuncSetAttribute(flash_kernel,
                       cudaFuncAttributeMaxDynamicSharedMemorySize, flash_smem);
  cudaFuncSetAttribute(proj_kernel,
                       cudaFuncAttributeMaxDynamicSharedMemorySize, proj_smem);

  // pre-pass: X transpose+bf16 pack, W bf16 pack
  xprep_kernel<<<dim3(NTOK/64, 4, 4), 256>>>(x);
  wprep_kernel<<<24, 256>>>(qkv_w);
  // QKV projection: all-bf16 -> packed fp8 Q/K + bf16 V scratch
  qkv_bf16_kernel<<<dim3(NTOK/64, 3, 4), 256, qkv_smem>>>(qkv_b);
  // fused fp8/bf16 attention, split-KV = 2
  flash_kernel<<<dim3(NTOK/128, 4, 2), 128, flash_smem>>>();
  // merge halves + normalize
  combine_kernel<<<dim3(64, 4), 256>>>();
  // output projection: M=256, K=64, tf32 single-stage
  proj_kernel<<<dim3(NTOK/64, 4, 4), 256, proj_smem>>>(proj_w, proj_b, out);
}